// round 2
// baseline (speedup 1.0000x reference)
#include <cuda_runtime.h>
#include <cstdint>
#include <cstddef>

// ---------------------------------------------------------------------------
// Scratch (device globals — no allocation allowed)
// ---------------------------------------------------------------------------
__device__ float g_noise[(size_t)1024 * 131072];   // 512 MiB: prescaled gumbel noise
__device__ float g_h1[64 * 8192];
__device__ float g_h2[64 * 8192];
__device__ float g_mask0[64 * 2048];
__device__ uint2 g_keys[1024];

// ---------------------------------------------------------------------------
// Threefry-2x32-20 (bit-exact JAX)
// ---------------------------------------------------------------------------
__device__ __forceinline__ void tf_block(uint32_t ks0, uint32_t ks1, uint32_t ks2,
                                         uint32_t x0, uint32_t x1,
                                         uint32_t& o0, uint32_t& o1)
{
    x0 += ks0; x1 += ks1;
#define TFR(r) { x0 += x1; x1 = __funnelshift_l(x1, x1, (r)); x1 ^= x0; }
    TFR(13); TFR(15); TFR(26); TFR(6);
    x0 += ks1; x1 += ks2 + 1u;
    TFR(17); TFR(29); TFR(16); TFR(24);
    x0 += ks2; x1 += ks0 + 2u;
    TFR(13); TFR(15); TFR(26); TFR(6);
    x0 += ks0; x1 += ks1 + 3u;
    TFR(17); TFR(29); TFR(16); TFR(24);
    x0 += ks1; x1 += ks2 + 4u;
    TFR(13); TFR(15); TFR(26); TFR(6);
    x0 += ks2; x1 += ks0 + 5u;
#undef TFR
    o0 = x0; o1 = x1;
}

// per-iteration folded keys: key_i = threefry((0,42), (0,i))
__global__ void keys_kernel()
{
    int i = threadIdx.x;
    uint32_t k1 = 0u, k2 = 42u;
    uint32_t o0, o1;
    tf_block(k1, k2, k1 ^ k2 ^ 0x1BD11BDAu, 0u, (uint32_t)i, o0, o1);
    g_keys[i] = make_uint2(o0, o1);
}

// bits -> n = -2*log2(-ln u)   (so iter loop does e = 2^(mask*C + n), C = 2*log2 e)
__device__ __forceinline__ float bits_to_noise(uint32_t bits)
{
    uint32_t mant = bits >> 9;                              // 23-bit mantissa
    float fl = __uint2float_rn(mant) * 1.1920928955078125e-07f; // exact m*2^-23
    float L;
    float d = 1.0f - fl;                                    // exact for fl >= 0.5
    if (d <= 0.015625f) {
        // -ln(1-d) = d + d^2/2 + d^3/3 + d^4/4  (rel err < 5e-9 for d<=2^-6)
        L = d * (1.0f + d * (0.5f + d * (0.3333333432674408f + d * 0.25f)));
    } else if (mant == 0u) {
        L = 87.336544750553109f;                            // -ln(2^-126) (u = tiny)
    } else {
        L = -0.69314718055994531f * __log2f(fl);
    }
    return -2.0f * __log2f(L);
}

// noise for all (i, j): grid (64, 1024), 256 thr, 8 elems/thread
__global__ __launch_bounds__(256) void noise_kernel()
{
    int i = blockIdx.y;
    uint2 key = g_keys[i];
    uint32_t k1 = key.x, k2 = key.y;
    uint32_t ks2 = k1 ^ k2 ^ 0x1BD11BDAu;
    uint32_t jbase = blockIdx.x * 2048u + threadIdx.x;
    float* out = g_noise + (size_t)i * 131072u;
#pragma unroll
    for (int t = 0; t < 8; t++) {
        uint32_t j = jbase + (uint32_t)t * 256u;
        uint32_t o0, o1;
        tf_block(k1, k2, ks2, 0u, j, o0, o1);
        out[j] = bits_to_noise(o0 ^ o1);
    }
}

// ---------------------------------------------------------------------------
// Fused GEMM (64 x N, fp32) + batch-BN (+ optional affine+ReLU)
// One CTA = full 64 rows x 64 cols -> BN stats computed in-CTA.
// 256 threads, 4x4 outputs each, double-buffered smem, 16-wide K steps.
// ---------------------------------------------------------------------------
template <bool AR>
__global__ __launch_bounds__(256) void gemm_bn(const float* __restrict__ X,
                                               const float* __restrict__ W,
                                               const float* __restrict__ bias,
                                               const float* __restrict__ gamma,
                                               const float* __restrict__ beta,
                                               float* __restrict__ Y,
                                               int K, int N)
{
    __shared__ float Xs[2][1024];   // [kk][m]   16 x 64
    __shared__ float Ws[2][1024];   // [kk][n]   16 x 64
    __shared__ float smean[64];
    __shared__ float sinv[64];

    const int tid = threadIdx.x;
    const int tx = tid & 15, ty = tid >> 4;
    const int cb = blockIdx.x * 64;

    const int lm = tid >> 2;          // X row     0..63
    const int lk = (tid & 3) << 2;    // X k-sub   0,4,8,12
    const int wk = tid >> 4;          // W k row   0..15
    const int wn = (tid & 15) << 2;   // W col-sub 0..60

    float acc[4][4] = {};

    // stage tile 0
    float4 xa = *reinterpret_cast<const float4*>(X + (size_t)lm * K + lk);
    float4 wa = *reinterpret_cast<const float4*>(W + (size_t)wk * N + cb + wn);
    Xs[0][(lk + 0) * 64 + lm] = xa.x;
    Xs[0][(lk + 1) * 64 + lm] = xa.y;
    Xs[0][(lk + 2) * 64 + lm] = xa.z;
    Xs[0][(lk + 3) * 64 + lm] = xa.w;
    *reinterpret_cast<float4*>(&Ws[0][wk * 64 + wn]) = wa;
    __syncthreads();

    const int nt = K >> 4;
    int buf = 0;
    for (int t = 0; t < nt; t++) {
        float4 xn, wn4;
        const bool more = (t + 1 < nt);
        if (more) {
            int k0 = (t + 1) << 4;
            xn  = *reinterpret_cast<const float4*>(X + (size_t)lm * K + k0 + lk);
            wn4 = *reinterpret_cast<const float4*>(W + (size_t)(k0 + wk) * N + cb + wn);
        }
#pragma unroll
        for (int kk = 0; kk < 16; kk++) {
            const float4 a4 = *reinterpret_cast<const float4*>(&Xs[buf][(kk << 6) + (ty << 2)]);
            const float4 b4 = *reinterpret_cast<const float4*>(&Ws[buf][(kk << 6) + (tx << 2)]);
            const float av[4] = {a4.x, a4.y, a4.z, a4.w};
            const float bv[4] = {b4.x, b4.y, b4.z, b4.w};
#pragma unroll
            for (int i2 = 0; i2 < 4; i2++)
#pragma unroll
                for (int j2 = 0; j2 < 4; j2++)
                    acc[i2][j2] = fmaf(av[i2], bv[j2], acc[i2][j2]);
        }
        if (more) {
            int nb = buf ^ 1;
            Xs[nb][(lk + 0) * 64 + lm] = xn.x;
            Xs[nb][(lk + 1) * 64 + lm] = xn.y;
            Xs[nb][(lk + 2) * 64 + lm] = xn.z;
            Xs[nb][(lk + 3) * 64 + lm] = xn.w;
            *reinterpret_cast<float4*>(&Ws[nb][wk * 64 + wn]) = wn4;
            buf = nb;
        }
        __syncthreads();
    }

    // ---- bias + BN stats (reuse smem) ----
#pragma unroll
    for (int j = 0; j < 4; j++) {
        float bj = bias[cb + (tx << 2) + j];
#pragma unroll
        for (int i = 0; i < 4; i++) acc[i][j] += bj;
    }
    float* rs  = &Xs[0][0];   // [16][64] partial sums
    float* rss = &Ws[0][0];   // [16][64] partial sumsq
#pragma unroll
    for (int j = 0; j < 4; j++) {
        float s  = acc[0][j] + acc[1][j] + acc[2][j] + acc[3][j];
        float ss = acc[0][j] * acc[0][j] + acc[1][j] * acc[1][j]
                 + acc[2][j] * acc[2][j] + acc[3][j] * acc[3][j];
        rs [ty * 64 + (tx << 2) + j] = s;
        rss[ty * 64 + (tx << 2) + j] = ss;
    }
    __syncthreads();
    if (tid < 64) {
        float s = 0.f, ss = 0.f;
#pragma unroll
        for (int t = 0; t < 16; t++) { s += rs[t * 64 + tid]; ss += rss[t * 64 + tid]; }
        float mean = s * 0.015625f;
        float var  = fmaf(-mean, mean, ss * 0.015625f);
        smean[tid] = mean;
        sinv[tid]  = rsqrtf(var + 1e-5f);
    }
    __syncthreads();

#pragma unroll
    for (int i = 0; i < 4; i++) {
        float4 o;
        float* op = reinterpret_cast<float*>(&o);
#pragma unroll
        for (int j = 0; j < 4; j++) {
            int col = (tx << 2) + j;
            float y = (acc[i][j] - smean[col]) * sinv[col];
            if (AR) {
                y = fmaf(y, gamma[cb + col], beta[cb + col]);
                y = fmaxf(y, 0.0f);
            }
            op[j] = y;
        }
        *reinterpret_cast<float4*>(Y + (size_t)((ty << 2) + i) * N + cb + (tx << 2)) = o;
    }
}

// ---------------------------------------------------------------------------
// Sequential gumbel-softmax-max loop: one CTA per row (64 CTAs, 1024 threads)
// ---------------------------------------------------------------------------
__device__ __forceinline__ float ex2f(float x)
{
    float y; asm("ex2.approx.f32 %0, %1;" : "=f"(y) : "f"(x)); return y;
}

__global__ __launch_bounds__(1024) void iter_kernel(float* __restrict__ zout)
{
    const int row  = blockIdx.x;
    const int tid  = threadIdx.x;
    const int lane = tid & 31, wid = tid >> 5;
    const float C = 2.8853900817779268f;   // 2*log2(e)

    const float2 mm = *reinterpret_cast<const float2*>(g_mask0 + row * 2048 + 2 * tid);
    float m0 = mm.x, m1 = mm.y;
    float z0 = 0.f, z1 = 0.f;

    __shared__ float wsum[32];
    __shared__ float sinv;

    const float2* np = reinterpret_cast<const float2*>(g_noise) + (size_t)row * 1024 + tid;
    float2 nx = np[0];

    for (int i = 0; i < 1024; i++) {
        float2 cur = nx;
        if (i < 1023) nx = np[(size_t)(i + 1) * 65536];   // prefetch next iteration

        float e0 = ex2f(fmaf(m0, C, cur.x));
        float e1 = ex2f(fmaf(m1, C, cur.y));
        float s = e0 + e1;
#pragma unroll
        for (int o = 16; o; o >>= 1) s += __shfl_xor_sync(0xffffffffu, s, o);
        if (lane == 0) wsum[wid] = s;
        __syncthreads();
        if (tid < 32) {
            float t = wsum[tid];
#pragma unroll
            for (int o = 16; o; o >>= 1) t += __shfl_xor_sync(0xffffffffu, t, o);
            if (tid == 0) {
                float r; asm("rcp.approx.f32 %0, %1;" : "=f"(r) : "f"(t));
                r = r * (2.0f - t * r);   // one Newton step
                sinv = r;
            }
        }
        __syncthreads();
        float r = sinv;
        m0 = e0 * r; m1 = e1 * r;
        z0 = fmaxf(z0, m0); z1 = fmaxf(z1, m1);
    }
    zout[row * 2048 + 2 * tid]     = z0;
    zout[row * 2048 + 2 * tid + 1] = z1;
}

// ---------------------------------------------------------------------------
// Launch
// ---------------------------------------------------------------------------
extern "C" void kernel_launch(void* const* d_in, const int* in_sizes, int n_in,
                              void* d_out, int out_size)
{
    const float* f   = (const float*)d_in[0];
    const float* W1  = (const float*)d_in[1];
    const float* b1  = (const float*)d_in[2];
    const float* g1  = (const float*)d_in[3];
    const float* be1 = (const float*)d_in[4];
    const float* W2  = (const float*)d_in[5];
    const float* b2  = (const float*)d_in[6];
    const float* g2  = (const float*)d_in[7];
    const float* be2 = (const float*)d_in[8];
    const float* W3  = (const float*)d_in[9];
    const float* b3  = (const float*)d_in[10];
    float* out = (float*)d_out;

    void *p1 = nullptr, *p2 = nullptr, *p3 = nullptr;
    cudaGetSymbolAddress(&p1, g_h1);
    cudaGetSymbolAddress(&p2, g_h2);
    cudaGetSymbolAddress(&p3, g_mask0);
    float* h1 = (float*)p1;
    float* h2 = (float*)p2;
    float* mk = (float*)p3;

    keys_kernel<<<1, 1024>>>();
    noise_kernel<<<dim3(64, 1024), 256>>>();

    gemm_bn<true ><<<128, 256>>>(f,  W1, b1, g1, be1, h1, 2048, 8192);
    gemm_bn<true ><<<128, 256>>>(h1, W2, b2, g2, be2, h2, 8192, 8192);
    gemm_bn<false><<< 32, 256>>>(h2, W3, b3, nullptr, nullptr, mk, 8192, 2048);

    iter_kernel<<<64, 1024>>>(out);
}

// round 3
// speedup vs baseline: 1.3100x; 1.3100x over previous
#include <cuda_runtime.h>
#include <cstdint>
#include <cstddef>

// ---------------------------------------------------------------------------
// Scratch (device globals — no allocation allowed)
// ---------------------------------------------------------------------------
__device__ float g_noise[(size_t)1024 * 131072];   // 512 MiB prescaled gumbel noise
__device__ float g_h1[64 * 8192];
__device__ float g_h2[64 * 8192];
__device__ float g_mask0[64 * 2048];
__device__ float g_p2[(size_t)2 * 64 * 8192];      // gemm2 K-split partials
__device__ float g_p3[(size_t)4 * 64 * 2048];      // gemm3 K-split partials
__device__ uint2 g_keys[1024];

// ---------------------------------------------------------------------------
// Threefry-2x32-20 (bit-exact JAX)
// ---------------------------------------------------------------------------
__device__ __forceinline__ void tf_block(uint32_t ks0, uint32_t ks1, uint32_t ks2,
                                         uint32_t x0, uint32_t x1,
                                         uint32_t& o0, uint32_t& o1)
{
    x0 += ks0; x1 += ks1;
#define TFR(r) { x0 += x1; x1 = __funnelshift_l(x1, x1, (r)); x1 ^= x0; }
    TFR(13); TFR(15); TFR(26); TFR(6);
    x0 += ks1; x1 += ks2 + 1u;
    TFR(17); TFR(29); TFR(16); TFR(24);
    x0 += ks2; x1 += ks0 + 2u;
    TFR(13); TFR(15); TFR(26); TFR(6);
    x0 += ks0; x1 += ks1 + 3u;
    TFR(17); TFR(29); TFR(16); TFR(24);
    x0 += ks1; x1 += ks2 + 4u;
    TFR(13); TFR(15); TFR(26); TFR(6);
    x0 += ks2; x1 += ks0 + 5u;
#undef TFR
    o0 = x0; o1 = x1;
}

// per-iteration folded keys: key_i = threefry((0,42), (0,i))
__global__ void keys_kernel()
{
    int i = threadIdx.x;
    uint32_t k1 = 0u, k2 = 42u;
    uint32_t o0, o1;
    tf_block(k1, k2, k1 ^ k2 ^ 0x1BD11BDAu, 0u, (uint32_t)i, o0, o1);
    g_keys[i] = make_uint2(o0, o1);
}

// bits -> n = -2*log2(-ln u)  so the iter loop is e = 2^(mask*C + n), C = 2*log2(e)
__device__ __forceinline__ float bits_to_noise(uint32_t bits)
{
    uint32_t mant = bits >> 9;
    float fl = __uint2float_rn(mant) * 1.1920928955078125e-07f;  // exact m*2^-23
    float L;
    float d = 1.0f - fl;                                         // exact for fl >= 0.5
    if (d <= 0.015625f) {
        L = d * (1.0f + d * (0.5f + d * (0.3333333432674408f + d * 0.25f)));
    } else if (mant == 0u) {
        L = 87.336544750553109f;                                 // -ln(2^-126)
    } else {
        L = -0.69314718055994531f * __log2f(fl);
    }
    return -2.0f * __log2f(L);
}

// One noise "block" = 2048 elements of iteration i = b>>6, chunk = b&63.
__device__ __forceinline__ void noise_body(int b)
{
    int i = b >> 6;
    uint2 key = g_keys[i];
    uint32_t k1 = key.x, k2 = key.y;
    uint32_t ks2 = k1 ^ k2 ^ 0x1BD11BDAu;
    uint32_t jbase = (uint32_t)(b & 63) * 2048u + threadIdx.x;
    float* out = g_noise + (size_t)i * 131072u;
#pragma unroll
    for (int t = 0; t < 8; t++) {
        uint32_t j = jbase + (uint32_t)t * 256u;
        uint32_t o0, o1;
        tf_block(k1, k2, ks2, 0u, j, o0, o1);
        out[j] = bits_to_noise(o0 ^ o1);
    }
}

// ---------------------------------------------------------------------------
// Fused GEMM (64 x N fp32, 64x64 tile/CTA, 256 thr, 4x4/thread, dbl-buffered)
// + role-split: CTAs past the GEMM grid generate gumbel noise (alu pipe).
// RAW=true  -> write raw partial sums (K-split), epilogue in reduce_bn.
// RAW=false -> in-CTA bias + batch-BN (+ affine + ReLU if AR).
// ---------------------------------------------------------------------------
template <bool AR, bool RAW, int COLTILES, int KSPLIT>
__global__ __launch_bounds__(256) void gemm_noise(const float* __restrict__ X,
                                                  const float* __restrict__ W,
                                                  const float* __restrict__ bias,
                                                  const float* __restrict__ gamma,
                                                  const float* __restrict__ beta,
                                                  float* __restrict__ Y,
                                                  int K, int N, int noiseBase)
{
    constexpr int GCTAS = COLTILES * KSPLIT;
    if (blockIdx.x >= GCTAS) {                    // noise role
        noise_body(noiseBase + (int)blockIdx.x - GCTAS);
        return;
    }

    __shared__ float Xs[2][1024];   // [kk][m]
    __shared__ float Ws[2][1024];   // [kk][n]
    __shared__ float smean[64];
    __shared__ float sinv[64];

    const int tid = threadIdx.x;
    const int tx = tid & 15, ty = tid >> 4;
    const int col = blockIdx.x % COLTILES;
    const int kc  = blockIdx.x / COLTILES;
    const int cb  = col * 64;
    const int Kc  = K / KSPLIT;
    const int k0  = kc * Kc;

    const int lm = tid >> 2;
    const int lk = (tid & 3) << 2;
    const int wk = tid >> 4;
    const int wn = (tid & 15) << 2;

    float acc[4][4] = {};

    float4 xa = *reinterpret_cast<const float4*>(X + (size_t)lm * K + k0 + lk);
    float4 wa = *reinterpret_cast<const float4*>(W + (size_t)(k0 + wk) * N + cb + wn);
    Xs[0][(lk + 0) * 64 + lm] = xa.x;
    Xs[0][(lk + 1) * 64 + lm] = xa.y;
    Xs[0][(lk + 2) * 64 + lm] = xa.z;
    Xs[0][(lk + 3) * 64 + lm] = xa.w;
    *reinterpret_cast<float4*>(&Ws[0][wk * 64 + wn]) = wa;
    __syncthreads();

    const int nt = Kc >> 4;
    int buf = 0;
    for (int t = 0; t < nt; t++) {
        float4 xn, wn4;
        const bool more = (t + 1 < nt);
        if (more) {
            int kk0 = k0 + ((t + 1) << 4);
            xn  = *reinterpret_cast<const float4*>(X + (size_t)lm * K + kk0 + lk);
            wn4 = *reinterpret_cast<const float4*>(W + (size_t)(kk0 + wk) * N + cb + wn);
        }
#pragma unroll
        for (int kk = 0; kk < 16; kk++) {
            const float4 a4 = *reinterpret_cast<const float4*>(&Xs[buf][(kk << 6) + (ty << 2)]);
            const float4 b4 = *reinterpret_cast<const float4*>(&Ws[buf][(kk << 6) + (tx << 2)]);
            const float av[4] = {a4.x, a4.y, a4.z, a4.w};
            const float bv[4] = {b4.x, b4.y, b4.z, b4.w};
#pragma unroll
            for (int i2 = 0; i2 < 4; i2++)
#pragma unroll
                for (int j2 = 0; j2 < 4; j2++)
                    acc[i2][j2] = fmaf(av[i2], bv[j2], acc[i2][j2]);
        }
        if (more) {
            int nb = buf ^ 1;
            Xs[nb][(lk + 0) * 64 + lm] = xn.x;
            Xs[nb][(lk + 1) * 64 + lm] = xn.y;
            Xs[nb][(lk + 2) * 64 + lm] = xn.z;
            Xs[nb][(lk + 3) * 64 + lm] = xn.w;
            *reinterpret_cast<float4*>(&Ws[nb][wk * 64 + wn]) = wn4;
            buf = nb;
        }
        __syncthreads();
    }

    if (RAW) {
        // raw partials: Y[kc][row][cb+col]
        float* dst = Y + (size_t)kc * 64 * N;
#pragma unroll
        for (int i = 0; i < 4; i++) {
            float4 o = make_float4(acc[i][0], acc[i][1], acc[i][2], acc[i][3]);
            *reinterpret_cast<float4*>(dst + (size_t)((ty << 2) + i) * N + cb + (tx << 2)) = o;
        }
        return;
    }

    // ---- in-CTA bias + BN ----
#pragma unroll
    for (int j = 0; j < 4; j++) {
        float bj = bias[cb + (tx << 2) + j];
#pragma unroll
        for (int i = 0; i < 4; i++) acc[i][j] += bj;
    }
    float* rs  = &Xs[0][0];
    float* rss = &Ws[0][0];
#pragma unroll
    for (int j = 0; j < 4; j++) {
        float s  = acc[0][j] + acc[1][j] + acc[2][j] + acc[3][j];
        float ss = acc[0][j] * acc[0][j] + acc[1][j] * acc[1][j]
                 + acc[2][j] * acc[2][j] + acc[3][j] * acc[3][j];
        rs [ty * 64 + (tx << 2) + j] = s;
        rss[ty * 64 + (tx << 2) + j] = ss;
    }
    __syncthreads();
    if (tid < 64) {
        float s = 0.f, ss = 0.f;
#pragma unroll
        for (int t = 0; t < 16; t++) { s += rs[t * 64 + tid]; ss += rss[t * 64 + tid]; }
        float mean = s * 0.015625f;
        float var  = fmaf(-mean, mean, ss * 0.015625f);
        smean[tid] = mean;
        sinv[tid]  = rsqrtf(var + 1e-5f);
    }
    __syncthreads();

#pragma unroll
    for (int i = 0; i < 4; i++) {
        float4 o;
        float* op = reinterpret_cast<float*>(&o);
#pragma unroll
        for (int j = 0; j < 4; j++) {
            int c = (tx << 2) + j;
            float y = (acc[i][j] - smean[c]) * sinv[c];
            if (AR) {
                y = fmaf(y, gamma[cb + c], beta[cb + c]);
                y = fmaxf(y, 0.0f);
            }
            op[j] = y;
        }
        *reinterpret_cast<float4*>(Y + (size_t)((ty << 2) + i) * N + cb + (tx << 2)) = o;
    }
}

// ---------------------------------------------------------------------------
// K-split reduce + bias + batch-BN (+ affine + ReLU). One thread per column.
// ---------------------------------------------------------------------------
template <bool AR, int S>
__global__ __launch_bounds__(256) void reduce_bn(const float* __restrict__ P,
                                                 const float* __restrict__ bias,
                                                 const float* __restrict__ gamma,
                                                 const float* __restrict__ beta,
                                                 float* __restrict__ Y, int N)
{
    const int c = blockIdx.x * 256 + threadIdx.x;
    const float b = bias[c];
    float s = 0.f, ss = 0.f;
#pragma unroll 4
    for (int r = 0; r < 64; r++) {
        float v = b;
#pragma unroll
        for (int q = 0; q < S; q++) v += P[((size_t)q * 64 + r) * N + c];
        s += v; ss += v * v;
    }
    const float mean = s * 0.015625f;
    const float inv  = rsqrtf(fmaf(-mean, mean, ss * 0.015625f) + 1e-5f);
    const float ga = AR ? gamma[c] : 1.0f;
    const float be = AR ? beta[c]  : 0.0f;
#pragma unroll 4
    for (int r = 0; r < 64; r++) {
        float v = b;
#pragma unroll
        for (int q = 0; q < S; q++) v += P[((size_t)q * 64 + r) * N + c];
        float y = (v - mean) * inv;
        if (AR) y = fmaxf(fmaf(y, ga, be), 0.0f);
        Y[(size_t)r * N + c] = y;
    }
}

// ---------------------------------------------------------------------------
// Sequential gumbel-softmax-max loop: one CTA per row.
// Single __syncthreads per iter (double-buffered partials, per-warp final
// reduce, rcp.approx without Newton).
// ---------------------------------------------------------------------------
__device__ __forceinline__ float ex2f(float x)
{
    float y; asm("ex2.approx.f32 %0, %1;" : "=f"(y) : "f"(x)); return y;
}

__global__ __launch_bounds__(1024) void iter_kernel(float* __restrict__ zout)
{
    const int row  = blockIdx.x;
    const int tid  = threadIdx.x;
    const int lane = tid & 31, wid = tid >> 5;
    const float C = 2.8853900817779268f;   // 2*log2(e)

    const float2 mm = *reinterpret_cast<const float2*>(g_mask0 + row * 2048 + 2 * tid);
    float m0 = mm.x, m1 = mm.y;
    float z0 = 0.f, z1 = 0.f;

    __shared__ float wsum[2][32];

    const float2* np = reinterpret_cast<const float2*>(g_noise) + (size_t)row * 1024 + tid;
    float2 nx = np[0];

    for (int i = 0; i < 1024; i++) {
        const float2 cur = nx;
        if (i < 1023) nx = np[(size_t)(i + 1) * 65536];

        const float e0 = ex2f(fmaf(m0, C, cur.x));
        const float e1 = ex2f(fmaf(m1, C, cur.y));
        float s = e0 + e1;
#pragma unroll
        for (int o = 16; o; o >>= 1) s += __shfl_xor_sync(0xffffffffu, s, o);
        if (lane == 0) wsum[i & 1][wid] = s;
        __syncthreads();
        float t = wsum[i & 1][lane];
#pragma unroll
        for (int o = 16; o; o >>= 1) t += __shfl_xor_sync(0xffffffffu, t, o);
        float r; asm("rcp.approx.f32 %0, %1;" : "=f"(r) : "f"(t));
        m0 = e0 * r; m1 = e1 * r;
        z0 = fmaxf(z0, m0); z1 = fmaxf(z1, m1);
    }
    *reinterpret_cast<float2*>(zout + row * 2048 + 2 * tid) = make_float2(z0, z1);
}

// ---------------------------------------------------------------------------
// Launch
// ---------------------------------------------------------------------------
extern "C" void kernel_launch(void* const* d_in, const int* in_sizes, int n_in,
                              void* d_out, int out_size)
{
    const float* f   = (const float*)d_in[0];
    const float* W1  = (const float*)d_in[1];
    const float* b1  = (const float*)d_in[2];
    const float* g1  = (const float*)d_in[3];
    const float* be1 = (const float*)d_in[4];
    const float* W2  = (const float*)d_in[5];
    const float* b2  = (const float*)d_in[6];
    const float* g2  = (const float*)d_in[7];
    const float* be2 = (const float*)d_in[8];
    const float* W3  = (const float*)d_in[9];
    const float* b3  = (const float*)d_in[10];
    float* out = (float*)d_out;

    void *p1 = nullptr, *p2 = nullptr, *p3 = nullptr, *pp2 = nullptr, *pp3 = nullptr;
    cudaGetSymbolAddress(&p1, g_h1);
    cudaGetSymbolAddress(&p2, g_h2);
    cudaGetSymbolAddress(&p3, g_mask0);
    cudaGetSymbolAddress(&pp2, g_p2);
    cudaGetSymbolAddress(&pp3, g_p3);
    float* h1 = (float*)p1;
    float* h2 = (float*)p2;
    float* mk = (float*)p3;
    float* q2 = (float*)pp2;
    float* q3 = (float*)pp3;

    // noise distribution across the three gemm launches (65536 blocks total)
    constexpr int NZ1 = 15360, NZ2 = 33280, NZ3 = 16896;

    keys_kernel<<<1, 1024>>>();

    // gemm1: 64x8192, K=2048, unsplit, fused BN+affine+ReLU
    gemm_noise<true,  false, 128, 1><<<128 + NZ1, 256>>>(f,  W1, b1, g1, be1, h1, 2048, 8192, 0);

    // gemm2: 64x8192, K=8192, K-split x2 -> raw partials
    gemm_noise<false, true,  128, 2><<<256 + NZ2, 256>>>(h1, W2, nullptr, nullptr, nullptr,
                                                         q2, 8192, 8192, NZ1);
    reduce_bn<true, 2><<<32, 256>>>(q2, b2, g2, be2, h2, 8192);

    // gemm3: 64x2048, K=8192, K-split x4 -> raw partials
    gemm_noise<false, true,  32, 4><<<128 + NZ3, 256>>>(h2, W3, nullptr, nullptr, nullptr,
                                                        q3, 8192, 2048, NZ1 + NZ2);
    reduce_bn<false, 4><<<8, 256>>>(q3, b3, nullptr, nullptr, mk, 2048);

    iter_kernel<<<64, 1024>>>(out);
}